// round 17
// baseline (speedup 1.0000x reference)
#include <cuda_runtime.h>
#include <cuda_fp16.h>
#include <cstdint>

#define D_IN 256
#define D_OUT 128
#define SEGSZ 64
#define N_SEQ 2048

namespace {
// Row strides in BYTES. All ≡ 16 (mod 128) so each 8-row ldmatrix tile hits
// banks 4r..4r+3 -> conflict-free.
constexpr int X_STB = 528;    // X: 256 halves + pad
constexpr int H_STB = 272;    // h row-major: 128 halves + pad
constexpr int P_STB = 144;    // P row-major: 64 halves + pad

// X region (33792 B) is dead after the GEMM mainloop; P and the softmax
// partial arrays overlay it (9216 + 1024 + 1024 = 11264 <= 33792).
constexpr int OFF_X  = 0;                   // 64*528  = 33792 B
constexpr int OFF_P  = 0;                   // 64*144  =  9216 B (overlay)
constexpr int OFF_PM = 9216;                // pmax[64][4] f32 = 1024 B (overlay)
constexpr int OFF_PS = 10240;               // psum[64][4] f32 = 1024 B (overlay)
constexpr int OFF_H  = 33792;               // 64*272  = 17408 B
constexpr int OFF_BS = OFF_H + 17408;       // 51200: 512 B
constexpr int SMEM_BYTES = OFF_BS + 512;    // 51712 B; x3 CTAs = 155136 B
} // namespace

// W in fp16 MMA B-fragment layout:
// g_wfrag16[(kk*16 + ng)*32 + lane] = uint2{
//   half2( W[kk*16+2lc  ][ng*8+lr], W[kk*16+2lc+1][ng*8+lr] ),
//   half2( W[kk*16+2lc+8][ng*8+lr], W[kk*16+2lc+9][ng*8+lr] ) }
__device__ uint2 g_wfrag16[16 * 16 * 32];   // 64 KB

__device__ __forceinline__ uint32_t h2bits(__half2 h) {
    return *reinterpret_cast<uint32_t*>(&h);
}

__device__ __forceinline__ void hmma(float* d, const uint32_t* a, const uint32_t* b) {
    asm volatile(
        "mma.sync.aligned.m16n8k16.row.col.f32.f16.f16.f32 "
        "{%0,%1,%2,%3}, {%4,%5,%6,%7}, {%8,%9}, {%0,%1,%2,%3};\n"
        : "+f"(d[0]), "+f"(d[1]), "+f"(d[2]), "+f"(d[3])
        : "r"(a[0]), "r"(a[1]), "r"(a[2]), "r"(a[3]), "r"(b[0]), "r"(b[1]));
}

__device__ __forceinline__ void ldsm4(uint32_t* r, uint32_t a) {
    asm volatile("ldmatrix.sync.aligned.m8n8.x4.shared.b16 {%0,%1,%2,%3}, [%4];"
        : "=r"(r[0]), "=r"(r[1]), "=r"(r[2]), "=r"(r[3]) : "r"(a));
}
__device__ __forceinline__ void ldsm2(uint32_t* r, uint32_t a) {
    asm volatile("ldmatrix.sync.aligned.m8n8.x2.shared.b16 {%0,%1}, [%2];"
        : "=r"(r[0]), "=r"(r[1]) : "r"(a));
}
__device__ __forceinline__ void ldsm2t(uint32_t* r, uint32_t a) {
    asm volatile("ldmatrix.sync.aligned.m8n8.x2.trans.shared.b16 {%0,%1}, [%2];"
        : "=r"(r[0]), "=r"(r[1]) : "r"(a));
}

__global__ __launch_bounds__(256)
void prep_w_kernel(const float* __restrict__ Wg) {
    int i = blockIdx.x * 256 + threadIdx.x;   // 0..8191
    int kk = i >> 9;          // 0..15
    int ng = (i >> 5) & 15;
    int ln = i & 31;
    int lr = ln >> 2, lc = ln & 3;
    int col = ng * 8 + lr;
    int k = kk * 16;
    __half2 b0 = __floats2half2_rn(Wg[(k + 2*lc    ) * D_OUT + col],
                                   Wg[(k + 2*lc + 1) * D_OUT + col]);
    __half2 b1 = __floats2half2_rn(Wg[(k + 2*lc + 8) * D_OUT + col],
                                   Wg[(k + 2*lc + 9) * D_OUT + col]);
    uint2 v;
    v.x = *reinterpret_cast<uint32_t*>(&b0);
    v.y = *reinterpret_cast<uint32_t*>(&b1);
    g_wfrag16[i] = v;
}

__global__ __launch_bounds__(256, 3)
void attn_hidden_kernel(const float* __restrict__ Xall,
                        const float* __restrict__ bg,
                        float* __restrict__ out)
{
    extern __shared__ char sm[];
    const uint32_t smb = (uint32_t)__cvta_generic_to_shared(sm);
    float* bs   = reinterpret_cast<float*>(sm + OFF_BS);
    float* pmax = reinterpret_cast<float*>(sm + OFF_PM);   // [64][4]
    float* psum = reinterpret_cast<float*>(sm + OFF_PS);   // [64][4]

    const int tid  = threadIdx.x;
    const int warp = tid >> 5;
    const int lane = tid & 31;
    const int lr   = lane >> 2;
    const int lc   = lane & 3;

    // 2x4 warp grid: GEMM/ctx warp tile = 32 rows x 32 cols; S: 32 x 16
    const int m0  = (warp & 1) * 32;
    const int nq  = warp >> 1;       // 0..3
    const int n0  = nq * 32;
    const int n0s = nq * 16;

    const int g = blockIdx.x;
    const float* Xg = Xall + (size_t)g * SEGSZ * D_IN;

    if (tid < D_OUT) bs[tid] = bg[tid];

    // ldmatrix per-lane base addresses
    const int l15 = lane & 15;
    const int khi = (lane >> 4) << 4;              // 0 or 16 bytes
    const uint32_t aX_base = smb + OFF_X + (m0 + l15) * X_STB + khi;
    const uint32_t aH_base = smb + OFF_H + (m0 + l15) * H_STB + khi;
    const uint32_t aP_base = smb + OFF_P + (m0 + l15) * P_STB + khi;
    const uint32_t bS_base = smb + OFF_H + (n0s + (lane & 7)) * H_STB + (((lane >> 3) & 1) << 4);
    const uint32_t bT_base = smb + OFF_H + l15 * H_STB + n0 * 2;

    // ---- stage ALL of X (64x256) fp32 -> fp16 smem, once ----
    #pragma unroll 4
    for (int t = 0; t < 16; ++t) {
        int j = tid + t * 256;        // 0..4095 float4s (64 rows x 64 float4)
        int row = j >> 6, q = j & 63;
        float4 x4 = *reinterpret_cast<const float4*>(Xg + row * D_IN + q * 4);
        __half2 h0 = __floats2half2_rn(x4.x, x4.y);
        __half2 h1 = __floats2half2_rn(x4.z, x4.w);
        uint2 v; v.x = h2bits(h0); v.y = h2bits(h1);
        *reinterpret_cast<uint2*>(sm + OFF_X + row * X_STB + q * 8) = v;
    }

    // W B-fragment register ring: 2 slots, prefetch distance 2.
    uint32_t bfr[2][4][2];
    #pragma unroll
    for (int s = 0; s < 2; ++s) {
        #pragma unroll
        for (int nt = 0; nt < 4; ++nt) {
            uint2 w = __ldg(&g_wfrag16[(s * 16 + nq * 4 + nt) * 32 + lane]);
            bfr[s][nt][0] = w.x; bfr[s][nt][1] = w.y;
        }
    }

    __syncthreads();   // Xs + bs ready

    // ================= GEMM: h = X(64x256) @ W(256x128), 16 k16 steps ======
    float acc[2][4][4];
    #pragma unroll
    for (int mt = 0; mt < 2; ++mt)
        #pragma unroll
        for (int nt = 0; nt < 4; ++nt)
            #pragma unroll
            for (int i = 0; i < 4; ++i) acc[mt][nt][i] = 0.f;

    #pragma unroll
    for (int kk = 0; kk < 16; ++kk) {
        const int cur = kk & 1;
        uint32_t af[2][4];
        #pragma unroll
        for (int mt = 0; mt < 2; ++mt)
            ldsm4(af[mt], aX_base + mt * 16 * X_STB + kk * 32);
        #pragma unroll
        for (int mt = 0; mt < 2; ++mt)
            #pragma unroll
            for (int nt = 0; nt < 4; ++nt)
                hmma(acc[mt][nt], af[mt], bfr[cur][nt]);
        const int nk = (kk + 2 < 16) ? kk + 2 : 15;
        #pragma unroll
        for (int nt = 0; nt < 4; ++nt) {
            uint2 w = __ldg(&g_wfrag16[(nk * 16 + nq * 4 + nt) * 32 + lane]);
            bfr[cur][nt][0] = w.x; bfr[cur][nt][1] = w.y;
        }
    }

    // epilogue: h (+bias) -> fp16, row-major only (transpose handled by ldsm2t)
    #pragma unroll
    for (int mt = 0; mt < 2; ++mt) {
        #pragma unroll
        for (int nt = 0; nt < 4; ++nt) {
            int row = m0 + mt * 16 + lr;
            int col = n0 + nt * 8 + 2 * lc;
            float d0 = acc[mt][nt][0] + bs[col];
            float d1 = acc[mt][nt][1] + bs[col + 1];
            float d2 = acc[mt][nt][2] + bs[col];
            float d3 = acc[mt][nt][3] + bs[col + 1];
            __half2 p01 = __floats2half2_rn(d0, d1);
            __half2 p23 = __floats2half2_rn(d2, d3);
            *reinterpret_cast<uint32_t*>(sm + OFF_H + row * H_STB + col * 2)       = h2bits(p01);
            *reinterpret_cast<uint32_t*>(sm + OFF_H + (row + 8) * H_STB + col * 2) = h2bits(p23);
        }
    }
    __syncthreads();

    // ================= S = h @ h^T  (64x64, K=128 -> 8 k16 steps) ==========
    // S stays in registers; softmax is done in-register with deferred
    // normalization (ctx rows scaled by 1/rowsum at the end).
    float accS[2][2][4];
    #pragma unroll
    for (int mt = 0; mt < 2; ++mt)
        #pragma unroll
        for (int nt = 0; nt < 2; ++nt)
            #pragma unroll
            for (int i = 0; i < 4; ++i) accS[mt][nt][i] = 0.f;

    #pragma unroll
    for (int kk = 0; kk < 8; ++kk) {
        uint32_t af[2][4];
        #pragma unroll
        for (int mt = 0; mt < 2; ++mt)
            ldsm4(af[mt], aH_base + mt * 16 * H_STB + kk * 32);
        uint32_t bf[2][2];
        #pragma unroll
        for (int nt = 0; nt < 2; ++nt)
            ldsm2(bf[nt], bS_base + nt * 8 * H_STB + kk * 32);
        #pragma unroll
        for (int mt = 0; mt < 2; ++mt)
            #pragma unroll
            for (int nt = 0; nt < 2; ++nt)
                hmma(accS[mt][nt], af[mt], bf[nt]);
    }

    // ---- per-row strip max over this warp's 16-col strip ----
    // Thread's 4 rows: (mt, h) -> row = m0 + mt*16 + lr + h*8
    {
        float mx[2][2];
        #pragma unroll
        for (int mt = 0; mt < 2; ++mt) {
            mx[mt][0] = fmaxf(fmaxf(accS[mt][0][0], accS[mt][0][1]),
                              fmaxf(accS[mt][1][0], accS[mt][1][1]));
            mx[mt][1] = fmaxf(fmaxf(accS[mt][0][2], accS[mt][0][3]),
                              fmaxf(accS[mt][1][2], accS[mt][1][3]));
        }
        #pragma unroll
        for (int mt = 0; mt < 2; ++mt)
            #pragma unroll
            for (int h = 0; h < 2; ++h) {
                mx[mt][h] = fmaxf(mx[mt][h], __shfl_xor_sync(0xffffffffu, mx[mt][h], 1));
                mx[mt][h] = fmaxf(mx[mt][h], __shfl_xor_sync(0xffffffffu, mx[mt][h], 2));
            }
        if (lc == 0) {
            #pragma unroll
            for (int mt = 0; mt < 2; ++mt)
                #pragma unroll
                for (int h = 0; h < 2; ++h)
                    pmax[(m0 + mt * 16 + lr + h * 8) * 4 + nq] = mx[mt][h];
        }
    }
    __syncthreads();

    // ---- exp(S - rowmax) in regs; strip sums; write unnormalized P fp16 ----
    #pragma unroll
    for (int mt = 0; mt < 2; ++mt) {
        #pragma unroll
        for (int h = 0; h < 2; ++h) {
            int row = m0 + mt * 16 + lr + h * 8;
            float4 pm = *reinterpret_cast<const float4*>(pmax + row * 4);
            float m = fmaxf(fmaxf(pm.x, pm.y), fmaxf(pm.z, pm.w));
            float s = 0.f;
            #pragma unroll
            for (int nt = 0; nt < 2; ++nt) {
                float e0 = __expf(accS[mt][nt][2 * h]     - m);
                float e1 = __expf(accS[mt][nt][2 * h + 1] - m);
                accS[mt][nt][2 * h]     = e0;
                accS[mt][nt][2 * h + 1] = e1;
                s += e0 + e1;
            }
            s += __shfl_xor_sync(0xffffffffu, s, 1);
            s += __shfl_xor_sync(0xffffffffu, s, 2);
            if (lc == 0) psum[row * 4 + nq] = s;
            // write the two half2s for this row
            #pragma unroll
            for (int nt = 0; nt < 2; ++nt) {
                __half2 e2 = __floats2half2_rn(accS[mt][nt][2 * h], accS[mt][nt][2 * h + 1]);
                int col = n0s + nt * 8 + 2 * lc;
                *reinterpret_cast<uint32_t*>(sm + OFF_P + row * P_STB + col * 2) = h2bits(e2);
            }
        }
    }
    __syncthreads();

    // ---- row inverse sums for this thread's ctx output rows ----
    float inv[2][2];
    #pragma unroll
    for (int mt = 0; mt < 2; ++mt)
        #pragma unroll
        for (int h = 0; h < 2; ++h) {
            int row = m0 + mt * 16 + lr + h * 8;
            float4 ps = *reinterpret_cast<const float4*>(psum + row * 4);
            inv[mt][h] = 1.0f / (ps.x + ps.y + ps.z + ps.w);
        }

    // ================= ctx = E(64x64) @ h(64x128), 4 k16 steps =============
    #pragma unroll
    for (int mt = 0; mt < 2; ++mt)
        #pragma unroll
        for (int nt = 0; nt < 4; ++nt)
            #pragma unroll
            for (int i = 0; i < 4; ++i) acc[mt][nt][i] = 0.f;

    #pragma unroll
    for (int kk = 0; kk < 4; ++kk) {
        uint32_t af[2][4];
        #pragma unroll
        for (int mt = 0; mt < 2; ++mt)
            ldsm4(af[mt], aP_base + mt * 16 * P_STB + kk * 32);
        uint32_t bf[4][2];
        #pragma unroll
        for (int nt = 0; nt < 4; ++nt)
            ldsm2t(bf[nt], bT_base + kk * 16 * H_STB + nt * 16);
        #pragma unroll
        for (int mt = 0; mt < 2; ++mt)
            #pragma unroll
            for (int nt = 0; nt < 4; ++nt)
                hmma(acc[mt][nt], af[mt], bf[nt]);
    }

    // store ctx (fp32) to gmem, scaling each row by its 1/rowsum
    #pragma unroll
    for (int mt = 0; mt < 2; ++mt) {
        #pragma unroll
        for (int nt = 0; nt < 4; ++nt) {
            size_t row = (size_t)g * SEGSZ + m0 + mt * 16 + lr;
            int col = n0 + nt * 8 + 2 * lc;
            *reinterpret_cast<float2*>(out + row * D_OUT + col) =
                make_float2(acc[mt][nt][0] * inv[mt][0], acc[mt][nt][1] * inv[mt][0]);
            *reinterpret_cast<float2*>(out + (row + 8) * D_OUT + col) =
                make_float2(acc[mt][nt][2] * inv[mt][1], acc[mt][nt][3] * inv[mt][1]);
        }
    }
}

extern "C" void kernel_launch(void* const* d_in, const int* in_sizes, int n_in,
                              void* d_out, int out_size) {
    (void)in_sizes; (void)n_in; (void)out_size;
    const float* X = (const float*)d_in[0];
    const float* W = (const float*)d_in[1];
    const float* b = (const float*)d_in[2];
    float* out = (float*)d_out;

    prep_w_kernel<<<32, 256>>>(W);   // 8192 uint2 fragments (64 KB)

    cudaFuncSetAttribute(attn_hidden_kernel,
                         cudaFuncAttributeMaxDynamicSharedMemorySize, SMEM_BYTES);
    attn_hidden_kernel<<<N_SEQ, 256, SMEM_BYTES>>>(X, b, out);
}